// round 16
// baseline (speedup 1.0000x reference)
#include <cuda_runtime.h>
#include <cuda_fp16.h>
#include <cstdint>

#define DDIM 512
#define KDIM 512
#define BM   128
#define NTH  512
#define NCH  32      // K chunks of 16 (f16)
#define NPAIR 16

// static scratch (no allocations allowed)
// B stored CHUNK-MAJOR and PRE-SWIZZLED: chunk c = k-cols [16c,16c+16) of all
// 512 rows, 16384 bytes, laid out exactly as the smem stage expects.
__device__ uint8_t g_cb[NCH * 16384];
__device__ float g_c2[KDIM];

// ---- smem layout (bytes, dynamic) ----
#define BSTG    16384u
#define OFF_A   0u                    // 128 rows x 1024B swizzled = 131072, resident
#define OFF_B   131072u               // 4 x 16384 -> 196608
#define OFF_C2  196608u               // 512*4 -> 198656
#define OFF_X2  198656u               // 128*4 -> 199168
#define OFF_RS  199168u               // 4*128*4 -> 201216
#define OFF_MB  201216u               // 2 mbarriers x 8B
#define SMEM_TOTAL 201280u

// ---------------- helpers ----------------
__device__ __forceinline__ float frcp(float a) {
    float r; asm("rcp.approx.ftz.f32 %0, %1;" : "=f"(r) : "f"(a)); return r;
}
__device__ __forceinline__ uint32_t pkh(float a, float b) {
    __half2 h = __floats2half2_rn(a, b);
    return *reinterpret_cast<uint32_t*>(&h);
}
__device__ __forceinline__ void ldsm4(uint32_t* r, uint32_t a) {
    asm volatile("ldmatrix.sync.aligned.m8n8.x4.shared.b16 {%0,%1,%2,%3}, [%4];"
                 : "=r"(r[0]), "=r"(r[1]), "=r"(r[2]), "=r"(r[3]) : "r"(a));
}
__device__ __forceinline__ void mma_f16(uint32_t* c, const uint32_t* a, uint32_t b0, uint32_t b1) {
    asm volatile("mma.sync.aligned.m16n8k16.row.col.f16.f16.f16.f16 "
                 "{%0,%1}, {%2,%3,%4,%5}, {%6,%7}, {%0,%1};"
                 : "+r"(c[0]), "+r"(c[1])
                 : "r"(a[0]), "r"(a[1]), "r"(a[2]), "r"(a[3]), "r"(b0), "r"(b1));
}
#define MBAR_INIT(a, c) asm volatile("mbarrier.init.shared.b64 [%0], %1;" :: "r"(a), "r"(c) : "memory")
#define MBAR_EXPECT(a, b) asm volatile("mbarrier.arrive.expect_tx.shared.b64 _, [%0], %1;" :: "r"(a), "r"(b) : "memory")
__device__ __forceinline__ void bulk_ld(uint32_t dst, const void* gsrc, uint32_t mbar) {
    asm volatile("cp.async.bulk.shared::cta.global.mbarrier::complete_tx::bytes "
                 "[%0], [%1], %2, [%3];"
                 :: "r"(dst), "l"(__cvta_generic_to_global(gsrc)), "r"(BSTG), "r"(mbar)
                 : "memory");
}
__device__ __forceinline__ void mbar_wait(uint32_t addr, uint32_t parity) {
    asm volatile(
        "{\n\t.reg .pred P;\n\t"
        "WL%=:\n\t"
        "mbarrier.try_wait.parity.acquire.cta.shared::cta.b64 P, [%0], %1, 0x989680;\n\t"
        "@P bra WD%=;\n\t"
        "bra WL%=;\n\t"
        "WD%=:\n\t}"
        :: "r"(addr), "r"(parity) : "memory");
}

// ---------------- prep: clusters -> fp16 pre-swizzled chunk-major, c2 fp32 ----------------
__global__ void prep_kernel(const float* __restrict__ clusters) {
    int k = blockIdx.x, tid = threadIdx.x;
    const float* row = clusters + (size_t)k * DDIM;
    float s = 0.f;
    for (int d = tid; d < DDIM; d += 128) {
        float v = row[d];
        s += v * v;
        uint32_t ch = (uint32_t)d >> 4;
        uint32_t seg = (((uint32_t)d >> 3) & 1u) << 4;
        uint32_t off = ch * 16384u + (uint32_t)k * 32u
                     + (seg ^ (((uint32_t)k & 4u) << 2)) + ((uint32_t)d & 7u) * 2u;
        *(__half*)(g_cb + off) = __float2half(v);
    }
    #pragma unroll
    for (int o = 16; o > 0; o >>= 1) s += __shfl_xor_sync(0xffffffffu, s, o);
    __shared__ float red[4];
    if ((tid & 31) == 0) red[tid >> 5] = s;
    __syncthreads();
    if (tid == 0) g_c2[k] = red[0] + red[1] + red[2] + red[3];
}

// ---------------- main fused kernel ----------------
// CTA: 128 rows x all 512 cols. 512 threads, warp grid 4(M) x 4(N), warp tile 32x128.
// f16 accumulators. A resident in smem; B fed by cp.async.bulk in PAIRS:
// two 16 KB chunks complete on ONE mbarrier (expect_tx = 32 KB), one
// __syncthreads per pair. 4 chunk-slots = 2 pair-slots in flight.
__global__ void __launch_bounds__(NTH, 1)
cluster_kernel(const float* __restrict__ x, float* __restrict__ out) {
    extern __shared__ char smem[];
    char*  smA = smem + OFF_A;
    float* c2s = (float*)(smem + OFF_C2);
    float* x2s = (float*)(smem + OFF_X2);
    float* rss = (float*)(smem + OFF_RS);

    const int tid = threadIdx.x, lane = tid & 31, wid = tid >> 5;
    const int wm = wid & 3, wn = wid >> 2;          // 4 x 4 warp grid
    const long row0 = (long)blockIdx.x * BM;
    const float* xblk = x + row0 * DDIM;

    const uint32_t sA  = (uint32_t)__cvta_generic_to_shared(smA);
    const uint32_t sB  = (uint32_t)__cvta_generic_to_shared(smem + OFF_B);
    const uint32_t sMB = (uint32_t)__cvta_generic_to_shared(smem + OFF_MB);

    // init mbarriers + kick off pairs 0 and 1 (chunks 0..3) during A conversion
    if (tid == 0) {
        MBAR_INIT(sMB + 0, 1);
        MBAR_INIT(sMB + 8, 1);
        #pragma unroll
        for (int p = 0; p < 2; p++) {
            MBAR_EXPECT(sMB + p * 8, 2 * BSTG);
            bulk_ld(sB + (2 * p + 0) * BSTG, g_cb + (size_t)(2 * p + 0) * BSTG, sMB + p * 8);
            bulk_ld(sB + (2 * p + 1) * BSTG, g_cb + (size_t)(2 * p + 1) * BSTG, sMB + p * 8);
        }
    }

    for (int i = tid; i < KDIM; i += NTH) c2s[i] = g_c2[i];

    // ---- A: convert x tile fp32 -> fp16 into swizzled resident smem, + ||x||^2 ----
    {
        const int arow = tid >> 2, aq = tid & 3;    // 4 threads per row, 128 floats each
        const float* src = xblk + (size_t)arow * DDIM;
        float x2a = 0.f;
        #pragma unroll
        for (int j = 0; j < 16; j++) {
            const int fc = aq * 8 + j * 32;         // float col
            float4 u = *(const float4*)(src + fc);
            float4 v = *(const float4*)(src + fc + 4);
            x2a += u.x * u.x + u.y * u.y + u.z * u.z + u.w * u.w;
            x2a += v.x * v.x + v.y * v.y + v.z * v.z + v.w * v.w;
            uint4 w = make_uint4(pkh(u.x, u.y), pkh(u.z, u.w), pkh(v.x, v.y), pkh(v.z, v.w));
            uint32_t cb = (uint32_t)(fc * 2);
            *(uint4*)(smA + arow * 1024 + (cb ^ ((arow & 7u) << 4))) = w;
        }
        x2a += __shfl_xor_sync(0xffffffffu, x2a, 1);
        x2a += __shfl_xor_sync(0xffffffffu, x2a, 2);
        if ((lane & 3) == 0) x2s[arow] = x2a;
    }
    __syncthreads();   // A + x2 + c2 + mbarrier inits visible to all threads

    uint32_t acc[2][16][2];
    #pragma unroll
    for (int mt = 0; mt < 2; mt++)
        #pragma unroll
        for (int nt = 0; nt < 16; nt++) { acc[mt][nt][0] = 0u; acc[mt][nt][1] = 0u; }

    const uint32_t lmr = lane & 15, lmc = (lane >> 4) * 16;
    const uint32_t xr  = (lmr & 7u) << 4;                        // A swizzle term
    const uint32_t aro0 = sA + (uint32_t)(wm * 32 + lmr) * 1024u;
    const uint32_t aro1 = aro0 + 16u * 1024u;
    const uint32_t bro = sB + (uint32_t)(wn * 128 + lmr) * 32u + (lmc ^ ((lmr & 4u) << 2));

    // ---- mainloop: 16 pairs (2 chunks each), one wait + one sync per pair ----
    #pragma unroll 2
    for (int p = 0; p < NPAIR; p++) {
        mbar_wait(sMB + (p & 1) * 8, (p >> 1) & 1);   // both chunks of pair p landed

        #pragma unroll
        for (int h = 0; h < 2; h++) {
            const int c = 2 * p + h;
            const uint32_t acb = ((uint32_t)(c * 32) + lmc) ^ xr;
            uint32_t a0[4], a1[4];
            ldsm4(a0, aro0 + acb);
            ldsm4(a1, aro1 + acb);
            const uint32_t bbase = bro + (c & 3) * BSTG;
            #pragma unroll
            for (int bt = 0; bt < 8; bt++) {
                uint32_t b[4];
                ldsm4(b, bbase + bt * 512);
                mma_f16(acc[0][2 * bt + 0], a0, b[0], b[2]);
                mma_f16(acc[0][2 * bt + 1], a0, b[1], b[3]);
                mma_f16(acc[1][2 * bt + 0], a1, b[0], b[2]);
                mma_f16(acc[1][2 * bt + 1], a1, b[1], b[3]);
            }
        }

        __syncthreads();   // all threads done reading pair p's two stages
        if (p + 2 < NPAIR && tid == 0) {
            const int c0 = 2 * p + 4;                  // reuse the stages just freed
            MBAR_EXPECT(sMB + (p & 1) * 8, 2 * BSTG);
            bulk_ld(sB + (c0 & 3) * BSTG,       g_cb + (size_t)c0 * BSTG,       sMB + (p & 1) * 8);
            bulk_ld(sB + ((c0 + 1) & 3) * BSTG, g_cb + (size_t)(c0 + 1) * BSTG, sMB + (p & 1) * 8);
        }
    }

    // ---- epilogue pass 1: q (fp32 math), pack q into acc as f16x2, row sums ----
    #pragma unroll
    for (int mt = 0; mt < 2; mt++) {
        #pragma unroll
        for (int rr = 0; rr < 2; rr++) {
            const int row = wm * 32 + mt * 16 + (lane >> 2) + rr * 8;
            const float x2v1 = x2s[row] + 1.f;     // 1 + ||x||^2
            float rsum = 0.f;
            #pragma unroll
            for (int nt = 0; nt < 16; nt++) {
                float2 f = __half22float2(*(__half2*)&acc[mt][nt][rr]);
                const int col = wn * 128 + nt * 8 + (lane & 3) * 2;
                float2 c2v = *(const float2*)&c2s[col];
                float q0 = frcp(fmaf(-2.f, f.x, x2v1 + c2v.x));
                float q1 = frcp(fmaf(-2.f, f.y, x2v1 + c2v.y));
                acc[mt][nt][rr] = pkh(q0, q1);
                rsum += q0 + q1;
            }
            rsum += __shfl_xor_sync(0xffffffffu, rsum, 1);
            rsum += __shfl_xor_sync(0xffffffffu, rsum, 2);
            if ((lane & 3) == 0) rss[wn * 128 + row] = rsum;
        }
    }
    __syncthreads();

    // ---- epilogue pass 2: unpack q, scale by 1/rowsum, store ----
    #pragma unroll
    for (int mt = 0; mt < 2; mt++) {
        #pragma unroll
        for (int rr = 0; rr < 2; rr++) {
            const int row = wm * 32 + mt * 16 + (lane >> 2) + rr * 8;
            const float inv = frcp(rss[row] + rss[128 + row] + rss[256 + row] + rss[384 + row]);
            float* orow = out + (row0 + row) * KDIM;
            #pragma unroll
            for (int nt = 0; nt < 16; nt++) {
                float2 f = __half22float2(*(__half2*)&acc[mt][nt][rr]);
                const int col = wn * 128 + nt * 8 + (lane & 3) * 2;
                *(float2*)&orow[col] = make_float2(f.x * inv, f.y * inv);
            }
        }
    }
}

extern "C" void kernel_launch(void* const* d_in, const int* in_sizes, int n_in,
                              void* d_out, int out_size) {
    const float* x        = (const float*)d_in[0];
    const float* clusters = (const float*)d_in[1];
    float* out = (float*)d_out;
    int n = in_sizes[0] / DDIM;   // 131072

    cudaFuncSetAttribute(cluster_kernel, cudaFuncAttributeMaxDynamicSharedMemorySize, SMEM_TOTAL);
    prep_kernel<<<KDIM, 128>>>(clusters);
    cluster_kernel<<<n / BM, NTH, SMEM_TOTAL>>>(x, out);
}

// round 17
// speedup vs baseline: 1.0678x; 1.0678x over previous
#include <cuda_runtime.h>
#include <cuda_fp16.h>
#include <cstdint>

#define DDIM 512
#define KDIM 512
#define BM   128
#define NTH  512
#define NCH  32      // K chunks of 16 (f16)
#define NST  4       // B ring stages

// static scratch (no allocations allowed)
// B stored CHUNK-MAJOR and PRE-SWIZZLED (chunk = 16 k-cols x 512 rows = 16 KB)
__device__ uint8_t g_cb[NCH * 16384];
__device__ float g_c2[KDIM];

// ---- smem layout (bytes, dynamic) ----
#define BSTG    16384u
#define OFF_A   0u                    // 128 rows x 1024B swizzled = 131072, resident
#define OFF_B   131072u               // 4 x 16384 -> 196608
#define OFF_C2  196608u               // 512*4 -> 198656
#define OFF_X2  198656u               // 128*4 -> 199168
#define OFF_RS  199168u               // 4*128*4 -> 201216
#define OFF_MB  201216u               // 4 mbarriers x 8B
#define SMEM_TOTAL 201280u

// ---------------- helpers ----------------
__device__ __forceinline__ float frcp(float a) {
    float r; asm("rcp.approx.ftz.f32 %0, %1;" : "=f"(r) : "f"(a)); return r;
}
__device__ __forceinline__ uint32_t pkh(float a, float b) {
    __half2 h = __floats2half2_rn(a, b);
    return *reinterpret_cast<uint32_t*>(&h);
}
__device__ __forceinline__ void ldsm4(uint32_t* r, uint32_t a) {
    asm volatile("ldmatrix.sync.aligned.m8n8.x4.shared.b16 {%0,%1,%2,%3}, [%4];"
                 : "=r"(r[0]), "=r"(r[1]), "=r"(r[2]), "=r"(r[3]) : "r"(a));
}
__device__ __forceinline__ void mma_f16(uint32_t* c, const uint32_t* a, uint32_t b0, uint32_t b1) {
    asm volatile("mma.sync.aligned.m16n8k16.row.col.f16.f16.f16.f16 "
                 "{%0,%1}, {%2,%3,%4,%5}, {%6,%7}, {%0,%1};"
                 : "+r"(c[0]), "+r"(c[1])
                 : "r"(a[0]), "r"(a[1]), "r"(a[2]), "r"(a[3]), "r"(b0), "r"(b1));
}
#define MBAR_INIT(a, c) asm volatile("mbarrier.init.shared.b64 [%0], %1;" :: "r"(a), "r"(c) : "memory")
#define MBAR_EXPECT(a, b) asm volatile("mbarrier.arrive.expect_tx.shared.b64 _, [%0], %1;" :: "r"(a), "r"(b) : "memory")
__device__ __forceinline__ void bulk_ld(uint32_t dst, const void* gsrc, uint32_t mbar) {
    asm volatile("cp.async.bulk.shared::cta.global.mbarrier::complete_tx::bytes "
                 "[%0], [%1], %2, [%3];"
                 :: "r"(dst), "l"(__cvta_generic_to_global(gsrc)), "r"(BSTG), "r"(mbar)
                 : "memory");
}
__device__ __forceinline__ void mbar_wait(uint32_t addr, uint32_t parity) {
    asm volatile(
        "{\n\t.reg .pred P;\n\t"
        "WL%=:\n\t"
        "mbarrier.try_wait.parity.acquire.cta.shared::cta.b64 P, [%0], %1, 0x989680;\n\t"
        "@P bra WD%=;\n\t"
        "bra WL%=;\n\t"
        "WD%=:\n\t}"
        :: "r"(addr), "r"(parity) : "memory");
}

// ---------------- prep: clusters -> fp16 pre-swizzled chunk-major, c2 fp32 ----------------
__global__ void prep_kernel(const float* __restrict__ clusters) {
    int k = blockIdx.x, tid = threadIdx.x;
    const float* row = clusters + (size_t)k * DDIM;
    float s = 0.f;
    for (int d = tid; d < DDIM; d += 128) {
        float v = row[d];
        s += v * v;
        uint32_t ch = (uint32_t)d >> 4;
        uint32_t seg = (((uint32_t)d >> 3) & 1u) << 4;
        uint32_t off = ch * 16384u + (uint32_t)k * 32u
                     + (seg ^ (((uint32_t)k & 4u) << 2)) + ((uint32_t)d & 7u) * 2u;
        *(__half*)(g_cb + off) = __float2half(v);
    }
    #pragma unroll
    for (int o = 16; o > 0; o >>= 1) s += __shfl_xor_sync(0xffffffffu, s, o);
    __shared__ float red[4];
    if ((tid & 31) == 0) red[tid >> 5] = s;
    __syncthreads();
    if (tid == 0) g_c2[k] = red[0] + red[1] + red[2] + red[3];
}

// ---------------- main fused kernel ----------------
// CTA: 128 rows x all 512 cols. 512 threads, warp grid 4(M) x 4(N), warp tile 32x128.
// A conversion STREAMED: prologue converts only chunks 0-7; stages 1-3 (chunks
// 8-31) convert inside the mainloop (LDG at even chunks, convert+STS at odd),
// hidden behind MMA. B fed by cp.async.bulk 4-stage ring (R15 champion).
__global__ void __launch_bounds__(NTH, 1)
cluster_kernel(const float* __restrict__ x, float* __restrict__ out) {
    extern __shared__ char smem[];
    char*  smA = smem + OFF_A;
    float* c2s = (float*)(smem + OFF_C2);
    float* x2s = (float*)(smem + OFF_X2);
    float* rss = (float*)(smem + OFF_RS);

    const int tid = threadIdx.x, lane = tid & 31, wid = tid >> 5;
    const int wm = wid & 3, wn = wid >> 2;          // 4 x 4 warp grid
    const long row0 = (long)blockIdx.x * BM;
    const float* xblk = x + row0 * DDIM;

    const uint32_t sA  = (uint32_t)__cvta_generic_to_shared(smA);
    const uint32_t sB  = (uint32_t)__cvta_generic_to_shared(smem + OFF_B);
    const uint32_t sMB = (uint32_t)__cvta_generic_to_shared(smem + OFF_MB);

    // init mbarriers + kick off first 3 B chunks (land during stage-0 conversion)
    if (tid == 0) {
        #pragma unroll
        for (int s = 0; s < NST; s++) MBAR_INIT(sMB + s * 8, 1);
        #pragma unroll
        for (int c = 0; c < 3; c++) {
            MBAR_EXPECT(sMB + c * 8, BSTG);
            bulk_ld(sB + c * BSTG, g_cb + (size_t)c * BSTG, sMB + c * 8);
        }
    }

    for (int i = tid; i < KDIM; i += NTH) c2s[i] = g_c2[i];

    // A-conversion thread mapping: 4 threads per row
    const int arow = tid >> 2, aq = tid & 3;
    const float* xrow = xblk + (size_t)arow * DDIM;
    const uint32_t asw = ((uint32_t)arow & 7u) << 4;
    const uint32_t abase = sA + (uint32_t)arow * 1024u;
    float x2a = 0.f;

    // ---- prologue: convert ONLY stage 0 (chunks 0-7, float cols 0-127) ----
    #pragma unroll
    for (int j = 0; j < 4; j++) {
        const int fc = aq * 8 + j * 32;
        float4 u = *(const float4*)(xrow + fc);
        float4 v = *(const float4*)(xrow + fc + 4);
        x2a += u.x * u.x + u.y * u.y + u.z * u.z + u.w * u.w;
        x2a += v.x * v.x + v.y * v.y + v.z * v.z + v.w * v.w;
        uint4 w = make_uint4(pkh(u.x, u.y), pkh(u.z, u.w), pkh(v.x, v.y), pkh(v.z, v.w));
        *(uint4*)(smem + (abase - sA) + (((uint32_t)(fc * 2)) ^ asw)) = w;
    }
    __syncthreads();   // stage-0 A + c2 + mbarrier inits visible

    uint32_t acc[2][16][2];
    #pragma unroll
    for (int mt = 0; mt < 2; mt++)
        #pragma unroll
        for (int nt = 0; nt < 16; nt++) { acc[mt][nt][0] = 0u; acc[mt][nt][1] = 0u; }

    const uint32_t lmr = lane & 15, lmc = (lane >> 4) * 16;
    const uint32_t xr  = (lmr & 7u) << 4;                        // A ldsm swizzle term
    const uint32_t aro0 = sA + (uint32_t)(wm * 32 + lmr) * 1024u;
    const uint32_t aro1 = aro0 + 16u * 1024u;
    const uint32_t bro = sB + (uint32_t)(wn * 128 + lmr) * 32u + (lmc ^ ((lmr & 4u) << 2));

    float4 ux, vx;     // in-flight x slice (loaded at even chunks, converted at odd)

    // ---- mainloop: 32 K-chunks; A stages 1-3 convert in-loop; 4-stage B ring ----
    #pragma unroll 4
    for (int c = 0; c < NCH; c++) {
        mbar_wait(sMB + (c & 3) * 8, (c >> 2) & 1);   // B(c) landed (acquire)

        // streamed A conversion for stage (c>>3)+1
        if ((c & 1) == 0 && c < 24) {
            const int jj = 4 + ((c >> 3) << 2) + ((c >> 1) & 3);
            const float* srcj = xrow + aq * 8 + jj * 32;
            ux = *(const float4*)(srcj);
            vx = *(const float4*)(srcj + 4);
        }
        if ((c & 1) == 1 && c < 25) {
            const int jj = 4 + (((c - 1) >> 3) << 2) + (((c - 1) >> 1) & 3);
            const int fc = aq * 8 + jj * 32;
            x2a += ux.x * ux.x + ux.y * ux.y + ux.z * ux.z + ux.w * ux.w;
            x2a += vx.x * vx.x + vx.y * vx.y + vx.z * vx.z + vx.w * vx.w;
            uint4 w = make_uint4(pkh(ux.x, ux.y), pkh(ux.z, ux.w), pkh(vx.x, vx.y), pkh(vx.z, vx.w));
            *(uint4*)(smem + (abase - sA) + (((uint32_t)(fc * 2)) ^ asw)) = w;
        }

        const uint32_t acb = ((uint32_t)(c * 32) + lmc) ^ xr;
        uint32_t a0[4], a1[4];
        ldsm4(a0, aro0 + acb);
        ldsm4(a1, aro1 + acb);
        const uint32_t bbase = bro + (c & 3) * BSTG;
        #pragma unroll
        for (int bt = 0; bt < 8; bt++) {
            uint32_t b[4];
            ldsm4(b, bbase + bt * 512);
            mma_f16(acc[0][2 * bt + 0], a0, b[0], b[2]);
            mma_f16(acc[0][2 * bt + 1], a0, b[1], b[3]);
            mma_f16(acc[1][2 * bt + 0], a1, b[0], b[2]);
            mma_f16(acc[1][2 * bt + 1], a1, b[1], b[3]);
        }

        __syncthreads();   // stage reuse guard + A-stage publication
        if (c + 3 < NCH && tid == 0) {
            const uint32_t st = (c + 3) & 3;
            MBAR_EXPECT(sMB + st * 8, BSTG);
            bulk_ld(sB + st * BSTG, g_cb + (size_t)(c + 3) * BSTG, sMB + st * 8);
        }
    }

    // publish ||x||^2 (accumulated across prologue + in-loop conversions)
    x2a += __shfl_xor_sync(0xffffffffu, x2a, 1);
    x2a += __shfl_xor_sync(0xffffffffu, x2a, 2);
    if ((lane & 3) == 0) x2s[arow] = x2a;
    __syncthreads();

    // ---- epilogue pass 1: q (fp32 math), pack q into acc as f16x2, row sums ----
    #pragma unroll
    for (int mt = 0; mt < 2; mt++) {
        #pragma unroll
        for (int rr = 0; rr < 2; rr++) {
            const int row = wm * 32 + mt * 16 + (lane >> 2) + rr * 8;
            const float x2v1 = x2s[row] + 1.f;     // 1 + ||x||^2
            float rsum = 0.f;
            #pragma unroll
            for (int nt = 0; nt < 16; nt++) {
                float2 f = __half22float2(*(__half2*)&acc[mt][nt][rr]);
                const int col = wn * 128 + nt * 8 + (lane & 3) * 2;
                float2 c2v = *(const float2*)&c2s[col];
                float q0 = frcp(fmaf(-2.f, f.x, x2v1 + c2v.x));
                float q1 = frcp(fmaf(-2.f, f.y, x2v1 + c2v.y));
                acc[mt][nt][rr] = pkh(q0, q1);
                rsum += q0 + q1;
            }
            rsum += __shfl_xor_sync(0xffffffffu, rsum, 1);
            rsum += __shfl_xor_sync(0xffffffffu, rsum, 2);
            if ((lane & 3) == 0) rss[wn * 128 + row] = rsum;
        }
    }
    __syncthreads();

    // ---- epilogue pass 2: unpack q, scale by 1/rowsum, store ----
    #pragma unroll
    for (int mt = 0; mt < 2; mt++) {
        #pragma unroll
        for (int rr = 0; rr < 2; rr++) {
            const int row = wm * 32 + mt * 16 + (lane >> 2) + rr * 8;
            const float inv = frcp(rss[row] + rss[128 + row] + rss[256 + row] + rss[384 + row]);
            float* orow = out + (row0 + row) * KDIM;
            #pragma unroll
            for (int nt = 0; nt < 16; nt++) {
                float2 f = __half22float2(*(__half2*)&acc[mt][nt][rr]);
                const int col = wn * 128 + nt * 8 + (lane & 3) * 2;
                *(float2*)&orow[col] = make_float2(f.x * inv, f.y * inv);
            }
        }
    }
}

extern "C" void kernel_launch(void* const* d_in, const int* in_sizes, int n_in,
                              void* d_out, int out_size) {
    const float* x        = (const float*)d_in[0];
    const float* clusters = (const float*)d_in[1];
    float* out = (float*)d_out;
    int n = in_sizes[0] / DDIM;   // 131072

    cudaFuncSetAttribute(cluster_kernel, cudaFuncAttributeMaxDynamicSharedMemorySize, SMEM_TOTAL);
    prep_kernel<<<KDIM, 128>>>(clusters);
    cluster_kernel<<<n / BM, NTH, SMEM_TOTAL>>>(x, out);
}